// round 12
// baseline (speedup 1.0000x reference)
#include <cuda_runtime.h>
#include <cstdint>

typedef unsigned long long ull;

#define Bb 2048
#define Tt 1000
#define Ii 40
#define Hh 16
#define TS 20
#define NCH (Tt/TS)
#define PADF 8
#define BSTR (TS*Ii + PADF)     /* 808 floats per chunk slot (3232B, 16B-aligned) */
#define CHBYTES (TS*Ii*4)       /* 3200B per chunk */

// -------- device-global scratch (no allocation allowed) --------
__device__ float2 g_wp[32*20];       // per neuron-branch nb: 20 weight pairs, pre-scaled by (1-a)(1-b)
__device__ float  g_alpha2[32];      // alpha[h] replicated per branch lane
__device__ float  g_betab[32];       // beta per neuron-branch
__device__ float2 g_w2[Hh];          // (W2[0][h], W2[1][h])
__device__ float2 g_b2c;
__device__ uint32_t g_tmask[Bb*Tt];  // per (b,t) 32-bit spike mask (bit nb, pair-duplicated) — 8MB

// -------- packed f32x2 helpers --------
__device__ __forceinline__ ull pk2(float a, float b){ ull r; asm("mov.b64 %0,{%1,%2};":"=l"(r):"f"(a),"f"(b)); return r; }
__device__ __forceinline__ void upk2(ull v, float&a, float&b){ asm("mov.b64 {%0,%1},%2;":"=f"(a),"=f"(b):"l"(v)); }
__device__ __forceinline__ ull fma2(ull a, ull b, ull c){ ull d; asm("fma.rn.f32x2 %0,%1,%2,%3;":"=l"(d):"l"(a),"l"(b),"l"(c)); return d; }
__device__ __forceinline__ ull mul2(ull a, ull b){ ull d; asm("mul.rn.f32x2 %0,%1,%2;":"=l"(d):"l"(a),"l"(b)); return d; }
__device__ __forceinline__ ull add2(ull a, ull b){ ull d; asm("add.rn.f32x2 %0,%1,%2;":"=l"(d):"l"(a),"l"(b)); return d; }
// non-volatile: allow ptxas to schedule loads across steps
__device__ __forceinline__ void lds128(uint32_t a, ull&u, ull&v){ asm("ld.shared.v2.b64 {%0,%1},[%2];":"=l"(u),"=l"(v):"r"(a)); }
__device__ __forceinline__ void stg32_lane0(int lane, uint32_t* p, uint32_t v){
  asm volatile("{ .reg .pred q; setp.eq.s32 q,%0,0; @q st.global.b32 [%1],%2; }"
               :: "r"(lane), "l"(p), "r"(v) : "memory");
}
// -------- TMA bulk copy + mbarrier --------
__device__ __forceinline__ void bulkcp(uint32_t dst, const void* src, uint32_t bytes, uint32_t bar){
  asm volatile("cp.async.bulk.shared::cta.global.mbarrier::complete_tx::bytes [%0],[%1],%2,[%3];"
               :: "r"(dst), "l"(src), "r"(bytes), "r"(bar) : "memory");
}
__device__ __forceinline__ void mbar_init(uint32_t bar, uint32_t cnt){
  asm volatile("mbarrier.init.shared.b64 [%0],%1;" :: "r"(bar), "r"(cnt) : "memory");
}
__device__ __forceinline__ void mbar_expect_tx(uint32_t bar, uint32_t bytes){
  asm volatile("mbarrier.arrive.expect_tx.shared.b64 _,[%0],%1;" :: "r"(bar), "r"(bytes) : "memory");
}
__device__ __forceinline__ void mbar_wait(uint32_t bar, uint32_t parity){
  uint32_t done;
  asm volatile("{\n\t.reg .pred p;\n\t"
               "mbarrier.try_wait.parity.acquire.cta.shared::cta.b64 p,[%1],%2;\n\t"
               "selp.b32 %0,1,0,p;\n\t}"
               : "=r"(done) : "r"(bar), "r"(parity) : "memory");
  if (!done){
    asm volatile("{\n\t.reg .pred P1;\n\t"
                 "WL_%=:\n\t"
                 "mbarrier.try_wait.parity.acquire.cta.shared::cta.b64 P1,[%0],%1,0x989680;\n\t"
                 "@P1 bra.uni WD_%=;\n\t"
                 "bra.uni WL_%=;\n\t"
                 "WD_%=:\n\t}"
                 :: "r"(bar), "r"(parity) : "memory");
  }
}

// ---------------- init: scalar outputs ----------------
__global__ void init_kernel(float* __restrict__ out, long long corrIdx, long long totIdx){
  if (threadIdx.x == 0){
    out[0] = 0.0f;
    out[corrIdx] = 0.0f;
    int cnt = 0;
    for (int t=0;t<Tt;t++) cnt += ((t>10) && (((t-10)%15)>5)) ? 1 : 0;
    out[totIdx] = (float)cnt * (float)Bb;   // flags.sum() * B
  }
}

// ---------------- pack: pre-scale weights per neuron-branch (parallel) ----------------
__global__ void pack_kernel(const float* __restrict__ W1, const float* __restrict__ tau_m,
                            const float* __restrict__ tau_n, const float* __restrict__ mask,
                            const float* __restrict__ W2, const float* __restrict__ b2){
  int tid = threadIdx.x;                    // 640 threads: (nb, k) pairs
  if (tid < 32*20){
    int nb = tid / 20, k = tid % 20;
    int h = nb >> 1;
    float a  = 1.0f/(1.0f + expf(-tau_m[h]));
    float be = 1.0f/(1.0f + expf(-tau_n[nb]));
    float s  = (1.0f - a)*(1.0f - be);      // fold (1-alpha)(1-beta) into weights
    int r = nb*Ii;
    g_wp[tid] = make_float2(W1[r+2*k]*mask[r+2*k]*s, W1[r+2*k+1]*mask[r+2*k+1]*s);
    if (k == 0){
      g_alpha2[nb] = a;
      g_betab[nb]  = be;
      if ((nb & 1) == 0) g_w2[h] = make_float2(W2[h], W2[Hh+h]);
    }
  }
  if (tid == 0) g_b2c = make_float2(b2[0], b2[1]);
}

// ---------------- main: warp = 1 batch, lane = neuron-branch (2048 warps) ----------------
// Same per-step structure as the 188.9us kernel (TMA staging, per-step ballot + predicated
// STG), ONLY the layout changed: each lane owns one branch's 40-wide dot (20 FFMA2, 2 chains);
// branch sum via shfl_xor(d,1). Doubles warps/SMSP (1.73 -> 3.46) for latency cover.
__global__ void __launch_bounds__(32) snn_kernel(const float* __restrict__ x){
  __shared__ __align__(16) float sx[2*BSTR];
  __shared__ __align__(8) ull smbar[2];
  const int lane = threadIdx.x;            // nb = 2h + br
  const int b    = blockIdx.x;

  ull w[20];
  #pragma unroll
  for (int k=0;k<20;k++){ float2 ww = g_wp[lane*20+k]; w[k]=pk2(ww.x,ww.y); }
  const float alpha = g_alpha2[lane];
  const float beta  = g_betab[lane];

  float d=0.f, mem=0.f, asel=0.f;
  uint32_t sbase = (uint32_t)__cvta_generic_to_shared(sx);
  uint32_t barb  = (uint32_t)__cvta_generic_to_shared(smbar);
  uint32_t* mrow = g_tmask + (size_t)b * Tt;
  const float* xg = x + (size_t)b * Tt * Ii;

  // init barriers + stage chunk 0 (single bulk copy)
  if (lane == 0){
    mbar_init(barb,     1);
    mbar_init(barb + 8, 1);
  }
  __syncwarp();
  if (lane == 0){
    mbar_expect_tx(barb, CHBYTES);
    bulkcp(sbase, xg, CHBYTES, barb);
  }

  int buf = 0;
  uint32_t pha0 = 0, pha1 = 0;
  for (int c=0;c<NCH;c++){
    if (lane == 0 && c+1 < NCH){
      uint32_t nb2 = barb + (uint32_t)((buf^1)*8);
      uint32_t sb  = sbase + (uint32_t)((buf^1)*BSTR)*4u;
      mbar_expect_tx(nb2, CHBYTES);
      bulkcp(sb, xg + (size_t)(c+1)*TS*Ii, CHBYTES, nb2);
    }
    if (buf == 0){ mbar_wait(barb,     pha0); pha0 ^= 1; }
    else         { mbar_wait(barb + 8, pha1); pha1 ^= 1; }

    uint32_t xaddr = sbase + (uint32_t)(buf*BSTR)*4u;

    #pragma unroll 4
    for (int tt=0; tt<TS; tt++){
      // dense dot, one branch: 10 LDS.128 broadcast -> 20 pairs, 2 FFMA2 chains
      ull pa, pb;
      lds128(xaddr, pa, pb);
      ull a0 = mul2(w[0], pa), a1 = mul2(w[1], pb);
      #pragma unroll
      for (int j=1;j<10;j++){
        ull xa, xb;
        lds128(xaddr + 16u*j, xa, xb);
        a0 = fma2(w[2*j],   xa, a0);
        a1 = fma2(w[2*j+1], xb, a1);
      }
      float f0,f1;
      ull s = add2(a0,a1); upk2(s,f0,f1);
      float cdot = f0+f1;                       // pre-scaled by (1-a)(1-b)

      // recurrence: branch state + cross-branch sum + membrane
      d = fmaf(beta, d, cdot);
      float l = d + __shfl_xor_sync(0xffffffffu, d, 1);
      mem = fmaf(alpha, mem, l) - asel;
      bool sp = mem > 1.0f;
      asel = sp ? alpha : 0.0f;                 // next-step reset, off critical path
      uint32_t m = __ballot_sync(0xffffffffu, sp);   // bit nb (pair-duplicated)
      stg32_lane0(lane, mrow + tt, m);

      xaddr += Ii*4;
    }
    mrow += TS;
    buf ^= 1;
  }
}

// ---------------- logits + fast closed-form loss + accuracy ----------------
// thread = one (b,t) point; mask bits pair-duplicated (neuron h at bit 2h).
__global__ void loss_kernel(const int* __restrict__ target, float* __restrict__ out,
                            long long corrIdx){
  __shared__ float2 lut[4][256];
  for (int m = threadIdx.x; m < 256; m += blockDim.x){
    #pragma unroll
    for (int q=0;q<4;q++){
      float2 a = make_float2(0.f,0.f);
      #pragma unroll
      for (int j=0;j<4;j++){
        if ((m>>(2*j))&1){ float2 v = g_w2[4*q+j]; a.x += v.x; a.y += v.y; }
      }
      lut[q][m] = a;
    }
  }
  __syncthreads();

  int idx = blockIdx.x * blockDim.x + threadIdx.x;
  float lossv = 0.f, corr = 0.f;
  if (idx < Bb*Tt){
    int t = idx % Tt;
    uint32_t m32 = g_tmask[idx];
    float2 c0 = lut[0][m32 & 0xFF];
    float2 c1 = lut[1][(m32>>8) & 0xFF];
    float2 c2 = lut[2][(m32>>16) & 0xFF];
    float2 c3 = lut[3][(m32>>24) & 0xFF];
    float2 b2v = g_b2c;
    float z0 = ((c0.x+c1.x)+(c2.x+c3.x)) + b2v.x;
    float z1 = ((c0.y+c1.y)+(c2.y+c3.y)) + b2v.y;
    out[1 + 2*(size_t)idx]     = z0;
    out[1 + 2*(size_t)idx + 1] = z1;
    if ((t>10) && (((t-10)%15)>5)){
      int tgt = target[idx];
      // closed-form double-softmax CE for 2 classes:
      // q = p1-p0 = (e^s-1)/(e^s+1), s = z1-z0
      // loss = ln2 ± q/2 + q^2/8 - q^4/192 + q^6/2880   (|q|<=1, err<3e-5)
      float s  = z1 - z0;
      float e  = __expf(s);
      float r  = __fdividef(1.0f, 1.0f + e);
      float q  = (e - 1.0f) * r;
      float q2 = q*q;
      float even = 0.6931471805599453f
                 + q2*(0.125f + q2*(-5.208333333e-3f + q2*3.472222222e-4f));
      float lossp = even + ((tgt==0) ? 0.5f : -0.5f) * q;
      lossv = lossp * (1.0f/(float)Bb);
      corr  = ((((s>0.0f)?1:0)==tgt)) ? 1.0f : 0.0f;
    }
  }
  #pragma unroll
  for (int off=16; off; off>>=1){
    lossv += __shfl_xor_sync(0xffffffffu, lossv, off);
    corr  += __shfl_xor_sync(0xffffffffu, corr,  off);
  }
  __shared__ float sl[32], sc[32];
  int wq = threadIdx.x>>5, ln = threadIdx.x&31;
  if (ln==0){ sl[wq]=lossv; sc[wq]=corr; }
  __syncthreads();
  if (wq==0){
    int nw = blockDim.x>>5;
    lossv = (ln<nw)? sl[ln]:0.f;
    corr  = (ln<nw)? sc[ln]:0.f;
    #pragma unroll
    for (int off=4; off; off>>=1){
      lossv += __shfl_xor_sync(0xffffffffu,lossv,off);
      corr  += __shfl_xor_sync(0xffffffffu,corr, off);
    }
    if (ln==0){ atomicAdd(out, lossv); atomicAdd(out+corrIdx, corr); }
  }
}

extern "C" void kernel_launch(void* const* d_in, const int* in_sizes, int n_in,
                              void* d_out, int out_size){
  const float* x      = (const float*)d_in[0];
  const int*   target = (const int*)  d_in[1];
  const float* W1     = (const float*)d_in[2];
  const float* tau_m  = (const float*)d_in[3];
  const float* tau_n  = (const float*)d_in[4];
  const float* mask   = (const float*)d_in[5];
  const float* W2     = (const float*)d_in[6];
  const float* b2     = (const float*)d_in[7];
  float* out = (float*)d_out;
  long long corrIdx = (long long)out_size - 2;   // layout: [loss, logits(B*T*2), correct, total]
  long long totIdx  = (long long)out_size - 1;

  init_kernel<<<1, 32>>>(out, corrIdx, totIdx);
  pack_kernel<<<1, 640>>>(W1, tau_m, tau_n, mask, W2, b2);
  snn_kernel<<<Bb, 32>>>(x);
  loss_kernel<<<(Bb*Tt + 255)/256, 256>>>(target, out, corrIdx);
}

// round 14
// speedup vs baseline: 1.0435x; 1.0435x over previous
#include <cuda_runtime.h>
#include <cstdint>

typedef unsigned long long ull;

#define Bb 2048
#define Tt 1000
#define Ii 40
#define Hh 16
#define TS 20
#define NCH (Tt/TS)
#define PADF 8
#define BSTR (TS*Ii + PADF)     /* 808 floats per batch-sub slot (16B aligned) */
#define BUFF (2*BSTR)           /* per-buffer floats (2 batch elems) */
#define CHBYTES (TS*Ii*4)       /* 3200B per batch per chunk */

// -------- device-global scratch (no allocation allowed) --------
__device__ float4 g_wpack[Hh*20];     // pre-scaled: branch0 pair *(oma*omb0), branch1 pair *(oma*omb1)
__device__ float  g_alpha[Hh];
__device__ float2 g_beta[Hh];
__device__ float2 g_w2[Hh];           // (W2[0][h], W2[1][h])
__device__ float2 g_b2c;

// -------- packed f32x2 helpers --------
__device__ __forceinline__ ull pk2(float a, float b){ ull r; asm("mov.b64 %0,{%1,%2};":"=l"(r):"f"(a),"f"(b)); return r; }
__device__ __forceinline__ void upk2(ull v, float&a, float&b){ asm("mov.b64 {%0,%1},%2;":"=f"(a),"=f"(b):"l"(v)); }
__device__ __forceinline__ ull fma2(ull a, ull b, ull c){ ull d; asm("fma.rn.f32x2 %0,%1,%2,%3;":"=l"(d):"l"(a),"l"(b),"l"(c)); return d; }
__device__ __forceinline__ ull mul2(ull a, ull b){ ull d; asm("mul.rn.f32x2 %0,%1,%2;":"=l"(d):"l"(a),"l"(b)); return d; }
__device__ __forceinline__ ull add2(ull a, ull b){ ull d; asm("add.rn.f32x2 %0,%1,%2;":"=l"(d):"l"(a),"l"(b)); return d; }
// non-volatile: allow ptxas to schedule loads across steps
__device__ __forceinline__ void lds128(uint32_t a, ull&u, ull&v){ asm("ld.shared.v2.b64 {%0,%1},[%2];":"=l"(u),"=l"(v):"r"(a)); }
__device__ __forceinline__ void sts32_lane0(int lane, uint32_t a, uint32_t v){
  asm volatile("{ .reg .pred q; setp.eq.s32 q,%0,0; @q st.shared.b32 [%1],%2; }"
               :: "r"(lane), "r"(a), "r"(v) : "memory");
}
// -------- TMA bulk copy + mbarrier --------
__device__ __forceinline__ void bulkcp(uint32_t dst, const void* src, uint32_t bytes, uint32_t bar){
  asm volatile("cp.async.bulk.shared::cta.global.mbarrier::complete_tx::bytes [%0],[%1],%2,[%3];"
               :: "r"(dst), "l"(src), "r"(bytes), "r"(bar) : "memory");
}
__device__ __forceinline__ void mbar_init(uint32_t bar, uint32_t cnt){
  asm volatile("mbarrier.init.shared.b64 [%0],%1;" :: "r"(bar), "r"(cnt) : "memory");
}
__device__ __forceinline__ void mbar_expect_tx(uint32_t bar, uint32_t bytes){
  asm volatile("mbarrier.arrive.expect_tx.shared.b64 _,[%0],%1;" :: "r"(bar), "r"(bytes) : "memory");
}
__device__ __forceinline__ void mbar_wait(uint32_t bar, uint32_t parity){
  uint32_t done;
  asm volatile("{\n\t.reg .pred p;\n\t"
               "mbarrier.try_wait.parity.acquire.cta.shared::cta.b64 p,[%1],%2;\n\t"
               "selp.b32 %0,1,0,p;\n\t}"
               : "=r"(done) : "r"(bar), "r"(parity) : "memory");
  if (!done){
    asm volatile("{\n\t.reg .pred P1;\n\t"
                 "WL_%=:\n\t"
                 "mbarrier.try_wait.parity.acquire.cta.shared::cta.b64 P1,[%0],%1,0x989680;\n\t"
                 "@P1 bra.uni WD_%=;\n\t"
                 "bra.uni WL_%=;\n\t"
                 "WD_%=:\n\t}"
                 :: "r"(bar), "r"(parity) : "memory");
  }
}

// ---------------- pack: pre-scale weights + init scalar outputs ----------------
__global__ void pack_kernel(const float* __restrict__ W1, const float* __restrict__ tau_m,
                            const float* __restrict__ tau_n, const float* __restrict__ mask,
                            const float* __restrict__ W2, const float* __restrict__ b2,
                            float* __restrict__ out, long long corrIdx, long long totIdx){
  int tid = threadIdx.x;                    // 320 threads: (h, k) pairs
  if (tid < Hh*20){
    int h = tid / 20, k = tid % 20;
    float a = 1.0f/(1.0f + expf(-tau_m[h]));
    float oma = 1.0f - a;
    float be0 = 1.0f/(1.0f+expf(-tau_n[h*2+0]));
    float be1 = 1.0f/(1.0f+expf(-tau_n[h*2+1]));
    float s0 = oma*(1.0f-be0);
    float s1 = oma*(1.0f-be1);
    int r0 = (2*h)*Ii, r1 = (2*h+1)*Ii;
    float4 w;
    w.x = W1[r0+2*k]  *mask[r0+2*k]  *s0;
    w.y = W1[r0+2*k+1]*mask[r0+2*k+1]*s0;
    w.z = W1[r1+2*k]  *mask[r1+2*k]  *s1;
    w.w = W1[r1+2*k+1]*mask[r1+2*k+1]*s1;
    g_wpack[h*20+k] = w;
    if (k == 0){
      g_alpha[h] = a;
      g_beta[h]  = make_float2(be0, be1);
      g_w2[h]    = make_float2(W2[h], W2[Hh+h]);
    }
  }
  if (tid == 0){
    g_b2c = make_float2(b2[0], b2[1]);
    out[0] = 0.0f;
    out[corrIdx] = 0.0f;
    int cnt = 0;
    for (int t=0;t<Tt;t++) cnt += ((t>10) && (((t-10)%15)>5)) ? 1 : 0;
    out[totIdx] = (float)cnt * (float)Bb;   // flags.sum() * B
  }
}

// ---------------- fused: SNN recurrence + logits + loss, warp = 2 batch x 16 neurons ----------------
// Hot loop identical to the 188.9us kernel; per-step mask store goes to shared; per-chunk
// epilogue decodes masks -> logits (LUT), writes logits (2x STG.32 — out+1 is only 4B
// aligned), accumulates closed-form CE + correct count; 2 atomicAdds per CTA at exit.
__global__ void __launch_bounds__(32) snn_kernel(const float* __restrict__ x,
                                                 const int* __restrict__ target,
                                                 float* __restrict__ out, long long corrIdx){
  __shared__ __align__(16) float sx[2*BUFF];
  __shared__ float2 lut0[256], lut1[256];   // logits contribution of 8-neuron sub-masks
  __shared__ uint32_t smask[TS];
  __shared__ __align__(8) ull smbar[2];
  const int lane = threadIdx.x;
  const int bsub = lane >> 4;
  const int h    = lane & 15;
  const int b0   = blockIdx.x * 2;

  ull wa[20], wb[20];
  #pragma unroll
  for (int k=0;k<20;k++){ float4 w = g_wpack[h*20+k]; wa[k]=pk2(w.x,w.y); wb[k]=pk2(w.z,w.w); }
  const float alpha = g_alpha[h];
  const float2 bt  = g_beta[h];
  const float2 b2v = g_b2c;

  // build LUTs (8 entries per lane)
  for (int m = lane; m < 256; m += 32){
    float2 a = make_float2(0.f,0.f), bb = make_float2(0.f,0.f);
    #pragma unroll
    for (int j=0;j<8;j++){
      if ((m>>j)&1){
        float2 w = g_w2[j];   a.x += w.x; a.y += w.y;
        float2 v = g_w2[8+j]; bb.x += v.x; bb.y += v.y;
      }
    }
    lut0[m]=a; lut1[m]=bb;
  }

  float d0=0.f, d1=0.f, mem=0.f;
  float asel = 0.f;
  float loss_acc = 0.f, corr_acc = 0.f;
  uint32_t sbase = (uint32_t)__cvta_generic_to_shared(sx);
  uint32_t barb  = (uint32_t)__cvta_generic_to_shared(smbar);
  uint32_t maskb = (uint32_t)__cvta_generic_to_shared(smask);

  const float* xg0 = x + (size_t)b0     * Tt * Ii;
  const float* xg1 = x + (size_t)(b0+1) * Tt * Ii;

  // init barriers + stage chunk 0
  if (lane == 0){
    mbar_init(barb,     1);
    mbar_init(barb + 8, 1);
  }
  __syncwarp();
  if (lane == 0){
    mbar_expect_tx(barb, 2*CHBYTES);
    bulkcp(sbase,            xg0, CHBYTES, barb);
    bulkcp(sbase + BSTR*4u,  xg1, CHBYTES, barb);
  }

  int buf = 0;
  uint32_t pha0 = 0, pha1 = 0;
  for (int c=0;c<NCH;c++){
    if (lane == 0 && c+1 < NCH){
      uint32_t nb   = barb + (uint32_t)((buf^1)*8);
      uint32_t sb   = sbase + (uint32_t)((buf^1)*BUFF)*4u;
      mbar_expect_tx(nb, 2*CHBYTES);
      bulkcp(sb,            xg0 + (size_t)(c+1)*TS*Ii, CHBYTES, nb);
      bulkcp(sb + BSTR*4u,  xg1 + (size_t)(c+1)*TS*Ii, CHBYTES, nb);
    }
    if (buf == 0){ mbar_wait(barb,     pha0); pha0 ^= 1; }
    else         { mbar_wait(barb + 8, pha1); pha1 ^= 1; }

    uint32_t xaddr = sbase + (uint32_t)(buf*BUFF + bsub*BSTR)*4u;

    #pragma unroll 4
    for (int tt=0; tt<TS; tt++){
      ull p0a, p0b;
      lds128(xaddr, p0a, p0b);
      ull a0 = mul2(wa[0], p0a), a1 = mul2(wa[1], p0b);
      ull q0 = mul2(wb[0], p0a), q1 = mul2(wb[1], p0b);
      #pragma unroll
      for (int j=1;j<10;j++){
        ull xa, xb;
        lds128(xaddr + 16u*j, xa, xb);
        a0 = fma2(wa[2*j],   xa, a0);
        a1 = fma2(wa[2*j+1], xb, a1);
        q0 = fma2(wb[2*j],   xa, q0);
        q1 = fma2(wb[2*j+1], xb, q1);
      }
      float f0,f1;
      ull s0 = add2(a0,a1); upk2(s0,f0,f1); float c0 = f0+f1;
      ull s1 = add2(q0,q1); upk2(s1,f0,f1); float c1 = f0+f1;

      d0 = fmaf(bt.x, d0, c0);
      d1 = fmaf(bt.y, d1, c1);
      float l = d0 + d1;
      mem = fmaf(alpha, mem, l) - asel;
      bool sp = mem > 1.0f;
      asel = sp ? alpha : 0.0f;
      uint32_t m = __ballot_sync(0xffffffffu, sp);
      sts32_lane0(lane, maskb + 4u*tt, m);       // shared instead of global

      xaddr += Ii*4;
    }
    __syncwarp();

    // ---- chunk epilogue: 40 points (2 batches x 20 steps), 2 rounds ----
    int tbase = c*TS;
    #pragma unroll
    for (int r=0; r<2; r++){
      int p = r*32 + lane;                       // point id
      if (p < 2*TS){
        int bs = p / TS;                         // 0/1: which batch
        int tr = p - bs*TS;
        int t  = tbase + tr;
        uint32_t w32 = smask[tr];
        uint32_t m16 = (w32 >> (bs<<4)) & 0xFFFFu;
        float2 lo = lut0[m16 & 0xFF];
        float2 hi = lut1[(m16 >> 8) & 0xFF];
        float z0 = lo.x + hi.x + b2v.x;
        float z1 = lo.y + hi.y + b2v.y;
        size_t idx = (size_t)(b0 + bs) * Tt + t;
        // out+1 is only 4B-aligned: two scalar stores (same L2 sectors, still coalesced)
        float* zp = out + 1 + 2*idx;
        zp[0] = z0;
        zp[1] = z1;
        if ((t>10) && (((t-10)%15)>5)){
          int tgt = target[idx];
          // closed-form double-softmax CE (2 classes): q=(e^s-1)/(e^s+1), s=z1-z0
          float s  = z1 - z0;
          float e  = __expf(s);
          float rr = __fdividef(1.0f, 1.0f + e);
          float q  = (e - 1.0f) * rr;
          float q2 = q*q;
          float even = 0.6931471805599453f
                     + q2*(0.125f + q2*(-5.208333333e-3f + q2*3.472222222e-4f));
          loss_acc += even + ((tgt==0) ? 0.5f : -0.5f) * q;
          corr_acc += ((((s>0.0f)?1:0)==tgt)) ? 1.0f : 0.0f;
        }
      }
    }
    __syncwarp();
    buf ^= 1;
  }

  // ---- final: warp-reduce loss/corr, 2 atomics per CTA ----
  #pragma unroll
  for (int off=16; off; off>>=1){
    loss_acc += __shfl_xor_sync(0xffffffffu, loss_acc, off);
    corr_acc += __shfl_xor_sync(0xffffffffu, corr_acc, off);
  }
  if (lane == 0){
    atomicAdd(out, loss_acc * (1.0f/(float)Bb));
    atomicAdd(out + corrIdx, corr_acc);
  }
}

extern "C" void kernel_launch(void* const* d_in, const int* in_sizes, int n_in,
                              void* d_out, int out_size){
  const float* x      = (const float*)d_in[0];
  const int*   target = (const int*)  d_in[1];
  const float* W1     = (const float*)d_in[2];
  const float* tau_m  = (const float*)d_in[3];
  const float* tau_n  = (const float*)d_in[4];
  const float* mask   = (const float*)d_in[5];
  const float* W2     = (const float*)d_in[6];
  const float* b2     = (const float*)d_in[7];
  float* out = (float*)d_out;
  long long corrIdx = (long long)out_size - 2;   // layout: [loss, logits(B*T*2), correct, total]
  long long totIdx  = (long long)out_size - 1;

  pack_kernel<<<1, 320>>>(W1, tau_m, tau_n, mask, W2, b2, out, corrIdx, totIdx);
  snn_kernel<<<Bb/2, 32>>>(x, target, out, corrIdx);
}